// round 14
// baseline (speedup 1.0000x reference)
#include <cuda_runtime.h>
#include <cuda_bf16.h>
#include <cstdio>
#include <cstdint>

// Problem constants: N=100000, E=1.6M, EL=200000
#define NMAX 100000
#define EMAX 1600000

// Scratch (static __device__ arrays — no allocation allowed)
__device__ float g_dis[NMAX];
__device__ int   g_cnt[NMAX];
__device__ int   g_rowptr[NMAX + 1];
__device__ int   g_cursor[NMAX];
__device__ int   g_bsums[1024];
__device__ int   g_esrc[EMAX];
__device__ float g_ewt[EMAX];
__device__ float g_h[NMAX * 128];    // gemm1 / gemm3 output
__device__ float g_h2[NMAX * 128];   // gemm2 output (avoids WAR with agg1_B)
__device__ float g_bufA[NMAX * 128];
__device__ float g_bufB[NMAX * 128];
// Fragment-ordered bf16 hi/lo weights (mma.sync .col B fragments)
__device__ __nv_bfloat16 g_w1h[128 * 128], g_w1l[128 * 128];
__device__ __nv_bfloat16 g_w2h[128 * 128], g_w2l[128 * 128];
__device__ __nv_bfloat16 g_w3h[64 * 128],  g_w3l[64 * 128];

// ---------------------------------------------------------------------------
// PTX helpers (baseline sm_80+ features only — no tcgen05 in this harness)
// ---------------------------------------------------------------------------
__device__ __forceinline__ uint32_t smem_u32(const void* p) {
    uint32_t a;
    asm("{ .reg .u64 t; cvta.to.shared.u64 t, %1; cvt.u32.u64 %0, t; }" : "=r"(a) : "l"(p));
    return a;
}
__device__ __forceinline__ void ldsm_x4(uint32_t* r, uint32_t addr) {
    asm volatile("ldmatrix.sync.aligned.m8n8.x4.shared.b16 {%0,%1,%2,%3}, [%4];"
                 : "=r"(r[0]), "=r"(r[1]), "=r"(r[2]), "=r"(r[3]) : "r"(addr));
}
__device__ __forceinline__ void mma16816(float* d, const uint32_t* a, uint32_t b0, uint32_t b1) {
    asm volatile("mma.sync.aligned.m16n8k16.row.col.f32.bf16.bf16.f32 "
                 "{%0,%1,%2,%3}, {%4,%5,%6,%7}, {%8,%9}, {%0,%1,%2,%3};"
                 : "+f"(d[0]), "+f"(d[1]), "+f"(d[2]), "+f"(d[3])
                 : "r"(a[0]), "r"(a[1]), "r"(a[2]), "r"(a[3]), "r"(b0), "r"(b1));
}
__device__ __forceinline__ uint32_t pack_bf2(float x, float y) {
    __nv_bfloat162 v;
    v.x = __float2bfloat16(x);
    v.y = __float2bfloat16(y);
    return *reinterpret_cast<uint32_t*>(&v);
}

// ---------------------------------------------------------------------------
// Weight prep -> fragment-ordered hi/lo arrays.
// ---------------------------------------------------------------------------
__global__ void prep_w_kernel(const float* __restrict__ W1, const float* __restrict__ W2,
                              const float* __restrict__ W3,
                              __nv_bfloat16* __restrict__ w1h, __nv_bfloat16* __restrict__ w1l,
                              __nv_bfloat16* __restrict__ w2h, __nv_bfloat16* __restrict__ w2l,
                              __nv_bfloat16* __restrict__ w3h, __nv_bfloat16* __restrict__ w3l)
{
    int i = blockIdx.x * blockDim.x + threadIdx.x;
    const float* W; uint2 *oh, *ol; int dout, j;
    if (i < 4096)       { W = W1; oh = (uint2*)w1h; ol = (uint2*)w1l; dout = 128; j = i; }
    else if (i < 8192)  { W = W2; oh = (uint2*)w2h; ol = (uint2*)w2l; dout = 128; j = i - 4096; }
    else if (i < 10240) { W = W3; oh = (uint2*)w3h; ol = (uint2*)w3l; dout = 64;  j = i - 8192; }
    else return;

    int lane  = j & 31;
    int ktile = (j >> 5) & 7;
    int ntile = j >> 8;
    int n  = ntile * 8 + (lane >> 2);
    int k0 = ktile * 16 + (lane & 3) * 2;

    float w00 = W[(k0 + 0) * dout + n];
    float w01 = W[(k0 + 1) * dout + n];
    float w10 = W[(k0 + 8) * dout + n];
    float w11 = W[(k0 + 9) * dout + n];

    __nv_bfloat16 h00 = __float2bfloat16(w00), h01 = __float2bfloat16(w01);
    __nv_bfloat16 h10 = __float2bfloat16(w10), h11 = __float2bfloat16(w11);

    uint2 hv, lv;
    hv.x = pack_bf2(w00, w01);
    hv.y = pack_bf2(w10, w11);
    lv.x = pack_bf2(w00 - __bfloat162float(h00), w01 - __bfloat162float(h01));
    lv.y = pack_bf2(w10 - __bfloat162float(h10), w11 - __bfloat162float(h11));
    oh[j] = hv;
    ol[j] = lv;
}

// ---------------------------------------------------------------------------
// mma.sync bf16-split GEMM: h = relu?(in) @ W   (R8 config: 64 regs, occ 4)
// Callers pass row-offset pointers to run a sub-range of rows.
// ---------------------------------------------------------------------------
template <int DOUT, bool RELU_IN>
__global__ void __launch_bounds__(256, 4)
gemm_mma_kernel(const float* __restrict__ in, const __nv_bfloat16* __restrict__ wtHi,
                const __nv_bfloat16* __restrict__ wtLo, float* __restrict__ h, int n)
{
    constexpr int THREADS = 256;
    constexpr int ROWS = 64;
    constexpr int K = 128;
    constexpr int PITCH = 136;
    constexpr int TN = DOUT / 4;
    constexpr int NT = TN / 8;
    constexpr int A_HI = 0;
    constexpr int A_LO = ROWS * PITCH;

    extern __shared__ __nv_bfloat16 smem[];
    const int t = threadIdx.x;
    const int row0 = blockIdx.x * ROWS;

    const float4* in4 = reinterpret_cast<const float4*>(in);
    #pragma unroll
    for (int i = t; i < ROWS * (K / 4); i += THREADS) {
        int r = i >> 5, c4 = i & 31;
        int gr = row0 + r;
        float4 v = make_float4(0.f, 0.f, 0.f, 0.f);
        if (gr < n) v = in4[(size_t)gr * (K / 4) + c4];
        if (RELU_IN) {
            v.x = fmaxf(v.x, 0.f); v.y = fmaxf(v.y, 0.f);
            v.z = fmaxf(v.z, 0.f); v.w = fmaxf(v.w, 0.f);
        }
        uint32_t h0 = pack_bf2(v.x, v.y);
        uint32_t h1 = pack_bf2(v.z, v.w);
        __nv_bfloat162 hh0 = *reinterpret_cast<__nv_bfloat162*>(&h0);
        __nv_bfloat162 hh1 = *reinterpret_cast<__nv_bfloat162*>(&h1);
        uint32_t l0 = pack_bf2(v.x - __bfloat162float(hh0.x), v.y - __bfloat162float(hh0.y));
        uint32_t l1 = pack_bf2(v.z - __bfloat162float(hh1.x), v.w - __bfloat162float(hh1.y));
        int off = r * PITCH + c4 * 4;
        *reinterpret_cast<uint2*>(smem + A_HI + off) = make_uint2(h0, h1);
        *reinterpret_cast<uint2*>(smem + A_LO + off) = make_uint2(l0, l1);
    }
    __syncthreads();

    const int wid  = t >> 5;
    const int lane = t & 31;
    const int warpM = wid >> 2;
    const int warpN = wid & 3;

    const int aRow = warpM * 32 + (lane & 15);
    const int aCol = (lane >> 4) * 8;
    const uint32_t sb = smem_u32(smem);
    const uint32_t aHiAddr = sb + (uint32_t)(A_HI + aRow * PITCH + aCol) * 2;
    const uint32_t aLoAddr = aHiAddr + (uint32_t)(A_LO - A_HI) * 2;

    const uint2* fH = reinterpret_cast<const uint2*>(wtHi);
    const uint2* fL = reinterpret_cast<const uint2*>(wtLo);
    const int fbase = (warpN * NT) * 256 + lane;

    float acc[2][NT][4];
    #pragma unroll
    for (int mt = 0; mt < 2; ++mt)
        #pragma unroll
        for (int nt = 0; nt < NT; ++nt)
            #pragma unroll
            for (int r = 0; r < 4; ++r) acc[mt][nt][r] = 0.f;

    #pragma unroll
    for (int kt = 0; kt < 8; ++kt) {
        const uint32_t ka = kt * 32;
        uint32_t ah[2][4], al[2][4];
        uint2 bh[NT], bl[NT];
        ldsm_x4(ah[0], aHiAddr + ka);
        ldsm_x4(ah[1], aHiAddr + ka + 16 * PITCH * 2);
        #pragma unroll
        for (int nt = 0; nt < NT; ++nt) bh[nt] = __ldg(&fH[fbase + nt * 256 + kt * 32]);
        #pragma unroll
        for (int nt = 0; nt < NT; ++nt) bl[nt] = __ldg(&fL[fbase + nt * 256 + kt * 32]);
        ldsm_x4(al[0], aLoAddr + ka);
        ldsm_x4(al[1], aLoAddr + ka + 16 * PITCH * 2);

        #pragma unroll
        for (int mt = 0; mt < 2; ++mt)
            #pragma unroll
            for (int nt = 0; nt < NT; ++nt)
                mma16816(acc[mt][nt], ah[mt], bh[nt].x, bh[nt].y);
        #pragma unroll
        for (int mt = 0; mt < 2; ++mt)
            #pragma unroll
            for (int nt = 0; nt < NT; ++nt)
                mma16816(acc[mt][nt], ah[mt], bl[nt].x, bl[nt].y);
        #pragma unroll
        for (int mt = 0; mt < 2; ++mt)
            #pragma unroll
            for (int nt = 0; nt < NT; ++nt)
                mma16816(acc[mt][nt], al[mt], bh[nt].x, bh[nt].y);
    }

    float2* h2 = reinterpret_cast<float2*>(h);
    #pragma unroll
    for (int mt = 0; mt < 2; ++mt) {
        #pragma unroll
        for (int nt = 0; nt < NT; ++nt) {
            int r = row0 + warpM * 32 + mt * 16 + (lane >> 2);
            int c = warpN * TN + nt * 8 + 2 * (lane & 3);
            if (r < n)
                h2[(size_t)r * (DOUT / 2) + c / 2] = make_float2(acc[mt][nt][0], acc[mt][nt][1]);
            if (r + 8 < n)
                h2[(size_t)(r + 8) * (DOUT / 2) + c / 2] = make_float2(acc[mt][nt][2], acc[mt][nt][3]);
        }
    }
}

// ---------------------------------------------------------------------------
// CSR build kernels
// ---------------------------------------------------------------------------
__global__ void zero_cnt_kernel(int* __restrict__ cnt, int n) {
    int i = blockIdx.x * blockDim.x + threadIdx.x;
    if (i < n) cnt[i] = 0;
}

__global__ void count_kernel(int* __restrict__ cnt, const int* __restrict__ dst, int E) {
    int e = blockIdx.x * blockDim.x + threadIdx.x;
    if (e < E) atomicAdd(&cnt[dst[e]], 1);
}

__global__ void scan1_kernel(const int* __restrict__ cnt, int* __restrict__ part,
                             int* __restrict__ sums, float* __restrict__ dis, int n) {
    __shared__ int sm[256];
    int t = threadIdx.x;
    int i = blockIdx.x * 256 + t;
    int v = (i < n) ? cnt[i] : 0;
    if (i < n) dis[i] = rsqrtf((float)(v + 1));
    sm[t] = v;
    __syncthreads();
    #pragma unroll
    for (int off = 1; off < 256; off <<= 1) {
        int a = (t >= off) ? sm[t - off] : 0;
        __syncthreads();
        sm[t] += a;
        __syncthreads();
    }
    if (i < n) part[i] = sm[t] - v;
    if (t == 255) sums[blockIdx.x] = sm[255];
}

__global__ void scan2_kernel(int* __restrict__ sums, int nb) {
    __shared__ int sm[1024];
    int t = threadIdx.x;
    int v = (t < nb) ? sums[t] : 0;
    sm[t] = v;
    __syncthreads();
    #pragma unroll
    for (int off = 1; off < 1024; off <<= 1) {
        int a = (t >= off) ? sm[t - off] : 0;
        __syncthreads();
        sm[t] += a;
        __syncthreads();
    }
    if (t < nb) sums[t] = sm[t] - v;
}

__global__ void scan3_kernel(const int* __restrict__ part, const int* __restrict__ sums,
                             int* __restrict__ row_ptr, int* __restrict__ cursor,
                             int n, int E) {
    int i = blockIdx.x * blockDim.x + threadIdx.x;
    if (i < n) {
        int v = part[i] + sums[i >> 8];
        row_ptr[i] = v;
        cursor[i] = v;
    }
    if (i == 0) row_ptr[n] = E;
}

__global__ void fill_kernel(const int* __restrict__ src, const int* __restrict__ dst,
                            const float* __restrict__ dis,
                            int* __restrict__ cursor, int* __restrict__ esrc,
                            float* __restrict__ ewt, int E) {
    int e = blockIdx.x * blockDim.x + threadIdx.x;
    if (e >= E) return;
    int s = src[e];
    int d = dst[e];
    int pos = atomicAdd(&cursor[d], 1);
    esrc[pos] = s;
    ewt[pos] = dis[s] * dis[d];
}

// ---------------------------------------------------------------------------
// CSR gather-aggregate with fused self-loop + bias, over node range
// [nodeBase, nodeEnd).  (R8 unroll-4: proven optimal; LTS-bound.)
// ---------------------------------------------------------------------------
template <int D>
__global__ void __launch_bounds__(256)
agg_kernel(const int* __restrict__ rp, const int* __restrict__ esrc,
           const float* __restrict__ ewt, const float* __restrict__ h,
           const float* __restrict__ dis, const float* __restrict__ bias,
           float* __restrict__ out, int nodeBase, int nodeEnd)
{
    constexpr int G = D / 4;
    int tid = blockIdx.x * blockDim.x + threadIdx.x;
    int node = nodeBase + tid / G;
    int li   = tid % G;
    if (node >= nodeEnd) return;

    int beg = rp[node];
    int end = rp[node + 1];

    const float4* h4 = reinterpret_cast<const float4*>(h);

    float d = dis[node];
    float dd = d * d;
    float4 hv = h4[(size_t)node * G + li];
    float4 b4 = reinterpret_cast<const float4*>(bias)[li];
    float4 acc;
    acc.x = fmaf(dd, hv.x, b4.x);
    acc.y = fmaf(dd, hv.y, b4.y);
    acc.z = fmaf(dd, hv.z, b4.z);
    acc.w = fmaf(dd, hv.w, b4.w);

    int j = beg;
    for (; j + 4 <= end; j += 4) {
        int s0 = esrc[j], s1 = esrc[j + 1], s2 = esrc[j + 2], s3 = esrc[j + 3];
        float w0 = ewt[j], w1 = ewt[j + 1], w2 = ewt[j + 2], w3 = ewt[j + 3];
        float4 v0 = h4[(size_t)s0 * G + li];
        float4 v1 = h4[(size_t)s1 * G + li];
        float4 v2 = h4[(size_t)s2 * G + li];
        float4 v3 = h4[(size_t)s3 * G + li];
        acc.x = fmaf(w0, v0.x, fmaf(w1, v1.x, fmaf(w2, v2.x, fmaf(w3, v3.x, acc.x))));
        acc.y = fmaf(w0, v0.y, fmaf(w1, v1.y, fmaf(w2, v2.y, fmaf(w3, v3.y, acc.y))));
        acc.z = fmaf(w0, v0.z, fmaf(w1, v1.z, fmaf(w2, v2.z, fmaf(w3, v3.z, acc.z))));
        acc.w = fmaf(w0, v0.w, fmaf(w1, v1.w, fmaf(w2, v2.w, fmaf(w3, v3.w, acc.w))));
    }
    for (; j < end; ++j) {
        int s = esrc[j];
        float w = ewt[j];
        float4 v = h4[(size_t)s * G + li];
        acc.x = fmaf(w, v.x, acc.x);
        acc.y = fmaf(w, v.y, acc.y);
        acc.z = fmaf(w, v.z, acc.z);
        acc.w = fmaf(w, v.w, acc.w);
    }

    reinterpret_cast<float4*>(out)[(size_t)node * G + li] = acc;
}

// ---------------------------------------------------------------------------
// Decode
// ---------------------------------------------------------------------------
__global__ void __launch_bounds__(256)
decode_kernel(const float* __restrict__ z, const int* __restrict__ eli,
              float* __restrict__ outh, float* __restrict__ outl, int EL)
{
    int tid = blockIdx.x * blockDim.x + threadIdx.x;
    int eid = tid >> 4;
    int li  = tid & 15;
    int lane = threadIdx.x & 31;
    unsigned mask = 0xFFFFu << (lane & 16);

    if (eid >= EL) return;

    int s = eli[eid];
    int t = eli[EL + eid];
    const float4* z4 = reinterpret_cast<const float4*>(z);
    float4 a = z4[(size_t)s * 16 + li];
    float4 b = z4[(size_t)t * 16 + li];

    float4 hh;
    hh.x = a.x * b.x; hh.y = a.y * b.y; hh.z = a.z * b.z; hh.w = a.w * b.w;

    float sum = hh.x + hh.y + hh.z + hh.w;
    float sq  = hh.x * hh.x + hh.y * hh.y + hh.z * hh.z + hh.w * hh.w;

    #pragma unroll
    for (int off = 8; off > 0; off >>= 1) {
        sum += __shfl_xor_sync(mask, sum, off);
        sq  += __shfl_xor_sync(mask, sq,  off);
    }

    float nrm = sqrtf(sq);
    float inv = 1.0f / fmaxf(nrm, 1e-12f);
    float4 o;
    o.x = hh.x * inv; o.y = hh.y * inv; o.z = hh.z * inv; o.w = hh.w * inv;
    reinterpret_cast<float4*>(outh)[(size_t)eid * 16 + li] = o;
    if (li == 0) outl[eid] = sum;
}

// ---------------------------------------------------------------------------
// Launch — two-stream graph:
//   branch s2: CSR build, then gemm halves of layers 2/3 (pipelined with agg)
//   branch s0: gemm1, agg halves, decode
// Row-range split at nA (multiple of 64) enables agg_l(B-half) to overlap
// gemm_{l+1}(A-half): gemm rows depend only on matching agg rows.
// Streams/events created per call, not destroyed (capture-safe; no device
// memory allocation APIs used).
// ---------------------------------------------------------------------------
extern "C" void kernel_launch(void* const* d_in, const int* in_sizes, int n_in,
                              void* d_out, int out_size)
{
    const float* x   = (const float*)d_in[0];
    const float* W1  = (const float*)d_in[1];
    const float* b1  = (const float*)d_in[2];
    const float* W2  = (const float*)d_in[3];
    const float* b2  = (const float*)d_in[4];
    const float* W3  = (const float*)d_in[5];
    const float* b3  = (const float*)d_in[6];
    const int*   ei  = (const int*)d_in[7];
    const int*   eli = (const int*)d_in[8];

    const int n  = in_sizes[0] / 128;
    const int E  = in_sizes[7] / 2;
    const int EL = in_sizes[8] / 2;

    float* out = (float*)d_out;
    float* out_hidden = out;
    float* out_logits = out + (size_t)EL * 64;

    float *d_dis, *d_h, *d_h2, *d_bufA, *d_bufB, *d_ewt;
    int *d_cnt, *d_rowptr, *d_cursor, *d_bsums, *d_esrc;
    __nv_bfloat16 *d_w1h, *d_w1l, *d_w2h, *d_w2l, *d_w3h, *d_w3l;
    cudaGetSymbolAddress((void**)&d_dis,    g_dis);
    cudaGetSymbolAddress((void**)&d_cnt,    g_cnt);
    cudaGetSymbolAddress((void**)&d_rowptr, g_rowptr);
    cudaGetSymbolAddress((void**)&d_cursor, g_cursor);
    cudaGetSymbolAddress((void**)&d_bsums,  g_bsums);
    cudaGetSymbolAddress((void**)&d_esrc,   g_esrc);
    cudaGetSymbolAddress((void**)&d_ewt,    g_ewt);
    cudaGetSymbolAddress((void**)&d_h,      g_h);
    cudaGetSymbolAddress((void**)&d_h2,     g_h2);
    cudaGetSymbolAddress((void**)&d_bufA,   g_bufA);
    cudaGetSymbolAddress((void**)&d_bufB,   g_bufB);
    cudaGetSymbolAddress((void**)&d_w1h,    g_w1h);
    cudaGetSymbolAddress((void**)&d_w1l,    g_w1l);
    cudaGetSymbolAddress((void**)&d_w2h,    g_w2h);
    cudaGetSymbolAddress((void**)&d_w2l,    g_w2l);
    cudaGetSymbolAddress((void**)&d_w3h,    g_w3h);
    cudaGetSymbolAddress((void**)&d_w3l,    g_w3l);

    constexpr int SMEM_A = 2 * 64 * 136 * 2;   // 34816
    cudaFuncSetAttribute(gemm_mma_kernel<128, false>, cudaFuncAttributeMaxDynamicSharedMemorySize, SMEM_A);
    cudaFuncSetAttribute(gemm_mma_kernel<128, true>,  cudaFuncAttributeMaxDynamicSharedMemorySize, SMEM_A);
    cudaFuncSetAttribute(gemm_mma_kernel<64,  true>,  cudaFuncAttributeMaxDynamicSharedMemorySize, SMEM_A);

    const int* src = ei;
    const int* dst = ei + E;

    const int nb = (n + 255) / 256;
    const int gemm_blocks = (n + 63) / 64;          // 1563
    const int gbA = (gemm_blocks + 1) / 2;          // 782
    const int nA  = gbA * 64;                       // 50048 (<= n)
    const int gbB = (n - nA + 63) / 64;             // blocks for rows [nA, n)

    const int aggA128 = (nA * 32 + 255) / 256;
    const int aggB128 = ((n - nA) * 32 + 255) / 256;
    const int agg64_blocks = (n * 16 + 255) / 256;

    // ---- Streams / events (created per call; capture-safe) ----
    cudaStream_t s2;
    cudaStreamCreateWithFlags(&s2, cudaStreamNonBlocking);
    cudaEvent_t evFork, evJoin, evA1, evB1, evG2, evA2, evB2, evG3;
    cudaEventCreateWithFlags(&evFork, cudaEventDisableTiming);
    cudaEventCreateWithFlags(&evJoin, cudaEventDisableTiming);
    cudaEventCreateWithFlags(&evA1,   cudaEventDisableTiming);
    cudaEventCreateWithFlags(&evB1,   cudaEventDisableTiming);
    cudaEventCreateWithFlags(&evG2,   cudaEventDisableTiming);
    cudaEventCreateWithFlags(&evA2,   cudaEventDisableTiming);
    cudaEventCreateWithFlags(&evB2,   cudaEventDisableTiming);
    cudaEventCreateWithFlags(&evG3,   cudaEventDisableTiming);

    cudaEventRecord(evFork, 0);
    cudaStreamWaitEvent(s2, evFork, 0);

    // Launch order keeps gemm1 as 4th launch (profiled slot).
    zero_cnt_kernel<<<nb, 256, 0, s2>>>(d_cnt, n);                                  // 1
    count_kernel<<<(E + 255) / 256, 256, 0, s2>>>(d_cnt, dst, E);                   // 2
    prep_w_kernel<<<40, 256>>>(W1, W2, W3, d_w1h, d_w1l, d_w2h, d_w2l, d_w3h, d_w3l); // 3
    gemm_mma_kernel<128, false><<<gemm_blocks, 256, SMEM_A>>>(x, d_w1h, d_w1l, d_h, n); // 4 (profiled)

    scan1_kernel<<<nb, 256, 0, s2>>>(d_cnt, d_cursor, d_bsums, d_dis, n);
    scan2_kernel<<<1, 1024, 0, s2>>>(d_bsums, nb);
    scan3_kernel<<<nb, 256, 0, s2>>>(d_cursor, d_bsums, d_rowptr, d_cursor, n, E);
    fill_kernel<<<(E + 255) / 256, 256, 0, s2>>>(src, dst, d_dis, d_cursor, d_esrc, d_ewt, E);
    cudaEventRecord(evJoin, s2);

    // ---- Layer 1 aggregate (s0), split in halves for pipelining ----
    cudaStreamWaitEvent(0, evJoin, 0);
    agg_kernel<128><<<aggA128, 256>>>(d_rowptr, d_esrc, d_ewt, d_h, d_dis, b1, d_bufA, 0, nA);
    cudaEventRecord(evA1, 0);
    agg_kernel<128><<<aggB128, 256>>>(d_rowptr, d_esrc, d_ewt, d_h, d_dis, b1, d_bufA, nA, n);
    cudaEventRecord(evB1, 0);

    // ---- Layer 2 GEMM halves on s2 (A overlaps agg1_B) -> g_h2 ----
    cudaStreamWaitEvent(s2, evA1, 0);
    gemm_mma_kernel<128, true><<<gbA, 256, SMEM_A, s2>>>(d_bufA, d_w2h, d_w2l, d_h2, nA);
    cudaStreamWaitEvent(s2, evB1, 0);
    gemm_mma_kernel<128, true><<<gbB, 256, SMEM_A, s2>>>(
        d_bufA + (size_t)nA * 128, d_w2h, d_w2l, d_h2 + (size_t)nA * 128, n - nA);
    cudaEventRecord(evG2, s2);

    // ---- Layer 2 aggregate halves on s0 ----
    cudaStreamWaitEvent(0, evG2, 0);
    agg_kernel<128><<<aggA128, 256>>>(d_rowptr, d_esrc, d_ewt, d_h2, d_dis, b2, d_bufB, 0, nA);
    cudaEventRecord(evA2, 0);
    agg_kernel<128><<<aggB128, 256>>>(d_rowptr, d_esrc, d_ewt, d_h2, d_dis, b2, d_bufB, nA, n);
    cudaEventRecord(evB2, 0);

    // ---- Layer 3 GEMM halves on s2 (A overlaps agg2_B) -> g_h (64-wide) ----
    cudaStreamWaitEvent(s2, evA2, 0);
    gemm_mma_kernel<64, true><<<gbA, 256, SMEM_A, s2>>>(d_bufB, d_w3h, d_w3l, d_h, nA);
    cudaStreamWaitEvent(s2, evB2, 0);
    gemm_mma_kernel<64, true><<<gbB, 256, SMEM_A, s2>>>(
        d_bufB + (size_t)nA * 128, d_w3h, d_w3l, d_h + (size_t)nA * 64, n - nA);
    cudaEventRecord(evG3, s2);

    // ---- Layer 3 aggregate (full) + decode on s0 ----
    cudaStreamWaitEvent(0, evG3, 0);
    agg_kernel<64><<<agg64_blocks, 256>>>(d_rowptr, d_esrc, d_ewt, d_h, d_dis, b3, d_bufA, 0, n);
    decode_kernel<<<((EL * 16) + 255) / 256, 256>>>(d_bufA, eli, out_hidden, out_logits, EL);
}

// round 15
// speedup vs baseline: 1.0343x; 1.0343x over previous
#include <cuda_runtime.h>
#include <cuda_bf16.h>
#include <cstdio>
#include <cstdint>

// Problem constants: N=100000, E=1.6M, EL=200000
#define NMAX 100000
#define EMAX 1600000

// Scratch (static __device__ arrays — no allocation allowed)
__device__ float g_dis[NMAX];
__device__ int   g_cnt[NMAX];
__device__ int   g_rowptr[NMAX + 1];
__device__ int   g_cursor[NMAX];
__device__ int   g_bsums[1024];
__device__ int   g_esrc[EMAX];
__device__ float g_ewt[EMAX];
__device__ float g_h[NMAX * 128];
__device__ float g_bufA[NMAX * 128];
__device__ float g_bufB[NMAX * 128];
// Fragment-ordered bf16 hi/lo weights (mma.sync .col B fragments)
__device__ __nv_bfloat16 g_w1h[128 * 128], g_w1l[128 * 128];
__device__ __nv_bfloat16 g_w2h[128 * 128], g_w2l[128 * 128];
__device__ __nv_bfloat16 g_w3h[64 * 128],  g_w3l[64 * 128];

// ---------------------------------------------------------------------------
// PTX helpers (baseline sm_80+ features only — no tcgen05 in this harness)
// ---------------------------------------------------------------------------
__device__ __forceinline__ uint32_t smem_u32(const void* p) {
    uint32_t a;
    asm("{ .reg .u64 t; cvta.to.shared.u64 t, %1; cvt.u32.u64 %0, t; }" : "=r"(a) : "l"(p));
    return a;
}
__device__ __forceinline__ void ldsm_x4(uint32_t* r, uint32_t addr) {
    asm volatile("ldmatrix.sync.aligned.m8n8.x4.shared.b16 {%0,%1,%2,%3}, [%4];"
                 : "=r"(r[0]), "=r"(r[1]), "=r"(r[2]), "=r"(r[3]) : "r"(addr));
}
__device__ __forceinline__ void mma16816(float* d, const uint32_t* a, uint32_t b0, uint32_t b1) {
    asm volatile("mma.sync.aligned.m16n8k16.row.col.f32.bf16.bf16.f32 "
                 "{%0,%1,%2,%3}, {%4,%5,%6,%7}, {%8,%9}, {%0,%1,%2,%3};"
                 : "+f"(d[0]), "+f"(d[1]), "+f"(d[2]), "+f"(d[3])
                 : "r"(a[0]), "r"(a[1]), "r"(a[2]), "r"(a[3]), "r"(b0), "r"(b1));
}
__device__ __forceinline__ uint32_t pack_bf2(float x, float y) {
    __nv_bfloat162 v;
    v.x = __float2bfloat16(x);
    v.y = __float2bfloat16(y);
    return *reinterpret_cast<uint32_t*>(&v);
}

// ---------------------------------------------------------------------------
// Weight prep -> fragment-ordered hi/lo arrays.
// Fragment entry j = (ntile*8 + ktile)*32 + lane:
//   n  = ntile*8 + lane/4 ; k0 = ktile*16 + (lane%4)*2
//   b0 = pack(B[k0][n], B[k0+1][n]),  b1 = pack(B[k0+8][n], B[k0+9][n])
// ---------------------------------------------------------------------------
__global__ void prep_w_kernel(const float* __restrict__ W1, const float* __restrict__ W2,
                              const float* __restrict__ W3,
                              __nv_bfloat16* __restrict__ w1h, __nv_bfloat16* __restrict__ w1l,
                              __nv_bfloat16* __restrict__ w2h, __nv_bfloat16* __restrict__ w2l,
                              __nv_bfloat16* __restrict__ w3h, __nv_bfloat16* __restrict__ w3l)
{
    int i = blockIdx.x * blockDim.x + threadIdx.x;
    const float* W; uint2 *oh, *ol; int dout, j;
    if (i < 4096)       { W = W1; oh = (uint2*)w1h; ol = (uint2*)w1l; dout = 128; j = i; }
    else if (i < 8192)  { W = W2; oh = (uint2*)w2h; ol = (uint2*)w2l; dout = 128; j = i - 4096; }
    else if (i < 10240) { W = W3; oh = (uint2*)w3h; ol = (uint2*)w3l; dout = 64;  j = i - 8192; }
    else return;

    int lane  = j & 31;
    int ktile = (j >> 5) & 7;
    int ntile = j >> 8;
    int n  = ntile * 8 + (lane >> 2);
    int k0 = ktile * 16 + (lane & 3) * 2;

    float w00 = W[(k0 + 0) * dout + n];
    float w01 = W[(k0 + 1) * dout + n];
    float w10 = W[(k0 + 8) * dout + n];
    float w11 = W[(k0 + 9) * dout + n];

    __nv_bfloat16 h00 = __float2bfloat16(w00), h01 = __float2bfloat16(w01);
    __nv_bfloat16 h10 = __float2bfloat16(w10), h11 = __float2bfloat16(w11);

    uint2 hv, lv;
    hv.x = pack_bf2(w00, w01);
    hv.y = pack_bf2(w10, w11);
    lv.x = pack_bf2(w00 - __bfloat162float(h00), w01 - __bfloat162float(h01));
    lv.y = pack_bf2(w10 - __bfloat162float(h10), w11 - __bfloat162float(h11));
    oh[j] = hv;
    ol[j] = lv;
}

// ---------------------------------------------------------------------------
// mma.sync bf16-split GEMM: h = relu?(in) @ W
// Block: 256 thr, 64 rows x DOUT cols, K=128. Warp grid 2x4.
// A staged in smem (hi/lo) + ldmatrix; B fragments LDG'd from fragment-
// ordered global arrays. 3 products: Ah*Bh + Ah*Bl + Al*Bh (fp32 accum).
// __launch_bounds__(256) (no min-blocks): ~80 regs so ALL per-kt fragment
// loads can be in flight simultaneously (64-reg clamp forced ptxas to
// reuse fragment registers, serializing load->MMA). Occ 3 CTAs = 24 warps.
// ---------------------------------------------------------------------------
template <int DOUT, bool RELU_IN>
__global__ void __launch_bounds__(256)
gemm_mma_kernel(const float* __restrict__ in, const __nv_bfloat16* __restrict__ wtHi,
                const __nv_bfloat16* __restrict__ wtLo, float* __restrict__ h, int n)
{
    constexpr int THREADS = 256;
    constexpr int ROWS = 64;
    constexpr int K = 128;
    constexpr int PITCH = 136;                   // halfwords per smem row
    constexpr int TN = DOUT / 4;                 // warp tile cols (32 or 16)
    constexpr int NT = TN / 8;                   // n-tiles per warp (4 or 2)
    constexpr int A_HI = 0;
    constexpr int A_LO = ROWS * PITCH;           // 8704

    extern __shared__ __nv_bfloat16 smem[];
    const int t = threadIdx.x;
    const int row0 = blockIdx.x * ROWS;

    // ---- Stage A (fp32 -> hi/lo bf16, ReLU folded) ----
    const float4* in4 = reinterpret_cast<const float4*>(in);
    #pragma unroll
    for (int i = t; i < ROWS * (K / 4); i += THREADS) {
        int r = i >> 5, c4 = i & 31;
        int gr = row0 + r;
        float4 v = make_float4(0.f, 0.f, 0.f, 0.f);
        if (gr < n) v = in4[(size_t)gr * (K / 4) + c4];
        if (RELU_IN) {
            v.x = fmaxf(v.x, 0.f); v.y = fmaxf(v.y, 0.f);
            v.z = fmaxf(v.z, 0.f); v.w = fmaxf(v.w, 0.f);
        }
        uint32_t h0 = pack_bf2(v.x, v.y);
        uint32_t h1 = pack_bf2(v.z, v.w);
        __nv_bfloat162 hh0 = *reinterpret_cast<__nv_bfloat162*>(&h0);
        __nv_bfloat162 hh1 = *reinterpret_cast<__nv_bfloat162*>(&h1);
        uint32_t l0 = pack_bf2(v.x - __bfloat162float(hh0.x), v.y - __bfloat162float(hh0.y));
        uint32_t l1 = pack_bf2(v.z - __bfloat162float(hh1.x), v.w - __bfloat162float(hh1.y));
        int off = r * PITCH + c4 * 4;
        *reinterpret_cast<uint2*>(smem + A_HI + off) = make_uint2(h0, h1);
        *reinterpret_cast<uint2*>(smem + A_LO + off) = make_uint2(l0, l1);
    }
    __syncthreads();

    // ---- Fragment addresses ----
    const int wid  = t >> 5;
    const int lane = t & 31;
    const int warpM = wid >> 2;   // 0..1
    const int warpN = wid & 3;    // 0..3

    const int aRow = warpM * 32 + (lane & 15);
    const int aCol = (lane >> 4) * 8;
    const uint32_t sb = smem_u32(smem);
    const uint32_t aHiAddr = sb + (uint32_t)(A_HI + aRow * PITCH + aCol) * 2;
    const uint32_t aLoAddr = aHiAddr + (uint32_t)(A_LO - A_HI) * 2;

    const uint2* fH = reinterpret_cast<const uint2*>(wtHi);
    const uint2* fL = reinterpret_cast<const uint2*>(wtLo);
    const int fbase = (warpN * NT) * 256 + lane;   // ntile stride = 8*32 = 256

    float acc[2][NT][4];
    #pragma unroll
    for (int mt = 0; mt < 2; ++mt)
        #pragma unroll
        for (int nt = 0; nt < NT; ++nt)
            #pragma unroll
            for (int r = 0; r < 4; ++r) acc[mt][nt][r] = 0.f;

    #pragma unroll
    for (int kt = 0; kt < 8; ++kt) {
        const uint32_t ka = kt * 32;          // 16 halfwords = 32 bytes per k-tile
        uint32_t ah[2][4], al[2][4];
        uint2 bh[NT], bl[NT];
        // Issue all loads up front — with ~80 regs these genuinely overlap
        ldsm_x4(ah[0], aHiAddr + ka);
        ldsm_x4(ah[1], aHiAddr + ka + 16 * PITCH * 2);
        #pragma unroll
        for (int nt = 0; nt < NT; ++nt) bh[nt] = __ldg(&fH[fbase + nt * 256 + kt * 32]);
        #pragma unroll
        for (int nt = 0; nt < NT; ++nt) bl[nt] = __ldg(&fL[fbase + nt * 256 + kt * 32]);
        ldsm_x4(al[0], aLoAddr + ka);
        ldsm_x4(al[1], aLoAddr + ka + 16 * PITCH * 2);

        // hi * hi
        #pragma unroll
        for (int mt = 0; mt < 2; ++mt)
            #pragma unroll
            for (int nt = 0; nt < NT; ++nt)
                mma16816(acc[mt][nt], ah[mt], bh[nt].x, bh[nt].y);
        // hi * lo
        #pragma unroll
        for (int mt = 0; mt < 2; ++mt)
            #pragma unroll
            for (int nt = 0; nt < NT; ++nt)
                mma16816(acc[mt][nt], ah[mt], bl[nt].x, bl[nt].y);
        // lo * hi
        #pragma unroll
        for (int mt = 0; mt < 2; ++mt)
            #pragma unroll
            for (int nt = 0; nt < NT; ++nt)
                mma16816(acc[mt][nt], al[mt], bh[nt].x, bh[nt].y);
    }

    // ---- Epilogue: direct float2 stores from fragments ----
    float2* h2 = reinterpret_cast<float2*>(h);
    #pragma unroll
    for (int mt = 0; mt < 2; ++mt) {
        #pragma unroll
        for (int nt = 0; nt < NT; ++nt) {
            int r = row0 + warpM * 32 + mt * 16 + (lane >> 2);
            int c = warpN * TN + nt * 8 + 2 * (lane & 3);
            if (r < n)
                h2[(size_t)r * (DOUT / 2) + c / 2] = make_float2(acc[mt][nt][0], acc[mt][nt][1]);
            if (r + 8 < n)
                h2[(size_t)(r + 8) * (DOUT / 2) + c / 2] = make_float2(acc[mt][nt][2], acc[mt][nt][3]);
        }
    }
}

// ---------------------------------------------------------------------------
// CSR build kernels
// ---------------------------------------------------------------------------
__global__ void zero_cnt_kernel(int* __restrict__ cnt, int n) {
    int i = blockIdx.x * blockDim.x + threadIdx.x;
    if (i < n) cnt[i] = 0;
}

__global__ void count_kernel(int* __restrict__ cnt, const int* __restrict__ dst, int E) {
    int e = blockIdx.x * blockDim.x + threadIdx.x;
    if (e < E) atomicAdd(&cnt[dst[e]], 1);
}

__global__ void scan1_kernel(const int* __restrict__ cnt, int* __restrict__ part,
                             int* __restrict__ sums, float* __restrict__ dis, int n) {
    __shared__ int sm[256];
    int t = threadIdx.x;
    int i = blockIdx.x * 256 + t;
    int v = (i < n) ? cnt[i] : 0;
    if (i < n) dis[i] = rsqrtf((float)(v + 1));
    sm[t] = v;
    __syncthreads();
    #pragma unroll
    for (int off = 1; off < 256; off <<= 1) {
        int a = (t >= off) ? sm[t - off] : 0;
        __syncthreads();
        sm[t] += a;
        __syncthreads();
    }
    if (i < n) part[i] = sm[t] - v;
    if (t == 255) sums[blockIdx.x] = sm[255];
}

__global__ void scan2_kernel(int* __restrict__ sums, int nb) {
    __shared__ int sm[1024];
    int t = threadIdx.x;
    int v = (t < nb) ? sums[t] : 0;
    sm[t] = v;
    __syncthreads();
    #pragma unroll
    for (int off = 1; off < 1024; off <<= 1) {
        int a = (t >= off) ? sm[t - off] : 0;
        __syncthreads();
        sm[t] += a;
        __syncthreads();
    }
    if (t < nb) sums[t] = sm[t] - v;
}

__global__ void scan3_kernel(const int* __restrict__ part, const int* __restrict__ sums,
                             int* __restrict__ row_ptr, int* __restrict__ cursor,
                             int n, int E) {
    int i = blockIdx.x * blockDim.x + threadIdx.x;
    if (i < n) {
        int v = part[i] + sums[i >> 8];
        row_ptr[i] = v;
        cursor[i] = v;
    }
    if (i == 0) row_ptr[n] = E;
}

__global__ void fill_kernel(const int* __restrict__ src, const int* __restrict__ dst,
                            const float* __restrict__ dis,
                            int* __restrict__ cursor, int* __restrict__ esrc,
                            float* __restrict__ ewt, int E) {
    int e = blockIdx.x * blockDim.x + threadIdx.x;
    if (e >= E) return;
    int s = src[e];
    int d = dst[e];
    int pos = atomicAdd(&cursor[d], 1);
    esrc[pos] = s;
    ewt[pos] = dis[s] * dis[d];
}

// ---------------------------------------------------------------------------
// CSR gather-aggregate with fused self-loop + bias (unroll-4: proven optimal)
// ---------------------------------------------------------------------------
template <int D>
__global__ void __launch_bounds__(256)
agg_kernel(const int* __restrict__ rp, const int* __restrict__ esrc,
           const float* __restrict__ ewt, const float* __restrict__ h,
           const float* __restrict__ dis, const float* __restrict__ bias,
           float* __restrict__ out, int n)
{
    constexpr int G = D / 4;
    int tid = blockIdx.x * blockDim.x + threadIdx.x;
    int node = tid / G;
    int li   = tid % G;
    if (node >= n) return;

    int beg = rp[node];
    int end = rp[node + 1];

    const float4* h4 = reinterpret_cast<const float4*>(h);

    float d = dis[node];
    float dd = d * d;
    float4 hv = h4[(size_t)node * G + li];
    float4 b4 = reinterpret_cast<const float4*>(bias)[li];
    float4 acc;
    acc.x = fmaf(dd, hv.x, b4.x);
    acc.y = fmaf(dd, hv.y, b4.y);
    acc.z = fmaf(dd, hv.z, b4.z);
    acc.w = fmaf(dd, hv.w, b4.w);

    int j = beg;
    for (; j + 4 <= end; j += 4) {
        int s0 = esrc[j], s1 = esrc[j + 1], s2 = esrc[j + 2], s3 = esrc[j + 3];
        float w0 = ewt[j], w1 = ewt[j + 1], w2 = ewt[j + 2], w3 = ewt[j + 3];
        float4 v0 = h4[(size_t)s0 * G + li];
        float4 v1 = h4[(size_t)s1 * G + li];
        float4 v2 = h4[(size_t)s2 * G + li];
        float4 v3 = h4[(size_t)s3 * G + li];
        acc.x = fmaf(w0, v0.x, fmaf(w1, v1.x, fmaf(w2, v2.x, fmaf(w3, v3.x, acc.x))));
        acc.y = fmaf(w0, v0.y, fmaf(w1, v1.y, fmaf(w2, v2.y, fmaf(w3, v3.y, acc.y))));
        acc.z = fmaf(w0, v0.z, fmaf(w1, v1.z, fmaf(w2, v2.z, fmaf(w3, v3.z, acc.z))));
        acc.w = fmaf(w0, v0.w, fmaf(w1, v1.w, fmaf(w2, v2.w, fmaf(w3, v3.w, acc.w))));
    }
    for (; j < end; ++j) {
        int s = esrc[j];
        float w = ewt[j];
        float4 v = h4[(size_t)s * G + li];
        acc.x = fmaf(w, v.x, acc.x);
        acc.y = fmaf(w, v.y, acc.y);
        acc.z = fmaf(w, v.z, acc.z);
        acc.w = fmaf(w, v.w, acc.w);
    }

    reinterpret_cast<float4*>(out)[(size_t)node * G + li] = acc;
}

// ---------------------------------------------------------------------------
// Decode
// ---------------------------------------------------------------------------
__global__ void __launch_bounds__(256)
decode_kernel(const float* __restrict__ z, const int* __restrict__ eli,
              float* __restrict__ outh, float* __restrict__ outl, int EL)
{
    int tid = blockIdx.x * blockDim.x + threadIdx.x;
    int eid = tid >> 4;
    int li  = tid & 15;
    int lane = threadIdx.x & 31;
    unsigned mask = 0xFFFFu << (lane & 16);

    if (eid >= EL) return;

    int s = eli[eid];
    int t = eli[EL + eid];
    const float4* z4 = reinterpret_cast<const float4*>(z);
    float4 a = z4[(size_t)s * 16 + li];
    float4 b = z4[(size_t)t * 16 + li];

    float4 hh;
    hh.x = a.x * b.x; hh.y = a.y * b.y; hh.z = a.z * b.z; hh.w = a.w * b.w;

    float sum = hh.x + hh.y + hh.z + hh.w;
    float sq  = hh.x * hh.x + hh.y * hh.y + hh.z * hh.z + hh.w * hh.w;

    #pragma unroll
    for (int off = 8; off > 0; off >>= 1) {
        sum += __shfl_xor_sync(mask, sum, off);
        sq  += __shfl_xor_sync(mask, sq,  off);
    }

    float nrm = sqrtf(sq);
    float inv = 1.0f / fmaxf(nrm, 1e-12f);
    float4 o;
    o.x = hh.x * inv; o.y = hh.y * inv; o.z = hh.z * inv; o.w = hh.w * inv;
    reinterpret_cast<float4*>(outh)[(size_t)eid * 16 + li] = o;
    if (li == 0) outl[eid] = sum;
}

// ---------------------------------------------------------------------------
// Launch — R13 structure: CSR build forked onto a second stream, concurrent
// with prep_w + gemm1 in the captured graph. Streams/events created per call
// and not destroyed (capture-safe; no device-memory allocation APIs).
// ---------------------------------------------------------------------------
extern "C" void kernel_launch(void* const* d_in, const int* in_sizes, int n_in,
                              void* d_out, int out_size)
{
    const float* x   = (const float*)d_in[0];
    const float* W1  = (const float*)d_in[1];
    const float* b1  = (const float*)d_in[2];
    const float* W2  = (const float*)d_in[3];
    const float* b2  = (const float*)d_in[4];
    const float* W3  = (const float*)d_in[5];
    const float* b3  = (const float*)d_in[6];
    const int*   ei  = (const int*)d_in[7];
    const int*   eli = (const int*)d_in[8];

    const int n  = in_sizes[0] / 128;
    const int E  = in_sizes[7] / 2;
    const int EL = in_sizes[8] / 2;

    float* out = (float*)d_out;
    float* out_hidden = out;
    float* out_logits = out + (size_t)EL * 64;

    float *d_dis, *d_h, *d_bufA, *d_bufB, *d_ewt;
    int *d_cnt, *d_rowptr, *d_cursor, *d_bsums, *d_esrc;
    __nv_bfloat16 *d_w1h, *d_w1l, *d_w2h, *d_w2l, *d_w3h, *d_w3l;
    cudaGetSymbolAddress((void**)&d_dis,    g_dis);
    cudaGetSymbolAddress((void**)&d_cnt,    g_cnt);
    cudaGetSymbolAddress((void**)&d_rowptr, g_rowptr);
    cudaGetSymbolAddress((void**)&d_cursor, g_cursor);
    cudaGetSymbolAddress((void**)&d_bsums,  g_bsums);
    cudaGetSymbolAddress((void**)&d_esrc,   g_esrc);
    cudaGetSymbolAddress((void**)&d_ewt,    g_ewt);
    cudaGetSymbolAddress((void**)&d_h,      g_h);
    cudaGetSymbolAddress((void**)&d_bufA,   g_bufA);
    cudaGetSymbolAddress((void**)&d_bufB,   g_bufB);
    cudaGetSymbolAddress((void**)&d_w1h,    g_w1h);
    cudaGetSymbolAddress((void**)&d_w1l,    g_w1l);
    cudaGetSymbolAddress((void**)&d_w2h,    g_w2h);
    cudaGetSymbolAddress((void**)&d_w2l,    g_w2l);
    cudaGetSymbolAddress((void**)&d_w3h,    g_w3h);
    cudaGetSymbolAddress((void**)&d_w3l,    g_w3l);

    // smem: A hi/lo only (2*64*136*2 B)
    constexpr int SMEM_A = 2 * 64 * 136 * 2;   // 34816
    cudaFuncSetAttribute(gemm_mma_kernel<128, false>, cudaFuncAttributeMaxDynamicSharedMemorySize, SMEM_A);
    cudaFuncSetAttribute(gemm_mma_kernel<128, true>,  cudaFuncAttributeMaxDynamicSharedMemorySize, SMEM_A);
    cudaFuncSetAttribute(gemm_mma_kernel<64,  true>,  cudaFuncAttributeMaxDynamicSharedMemorySize, SMEM_A);

    const int* src = ei;
    const int* dst = ei + E;

    const int nb = (n + 255) / 256;
    const int gemm_blocks = (n + 63) / 64;
    const int agg128_blocks = ((n * 32) + 255) / 256;
    const int agg64_blocks  = ((n * 16) + 255) / 256;

    // ---- Fork a side stream for the CSR build ----
    cudaStream_t s2;
    cudaStreamCreateWithFlags(&s2, cudaStreamNonBlocking);
    cudaEvent_t evFork, evJoin;
    cudaEventCreateWithFlags(&evFork, cudaEventDisableTiming);
    cudaEventCreateWithFlags(&evJoin, cudaEventDisableTiming);

    cudaEventRecord(evFork, 0);
    cudaStreamWaitEvent(s2, evFork, 0);

    // Branch A (s2): CSR build — independent of weights/gemm1
    zero_cnt_kernel<<<nb, 256, 0, s2>>>(d_cnt, n);
    count_kernel<<<(E + 255) / 256, 256, 0, s2>>>(d_cnt, dst, E);
    scan1_kernel<<<nb, 256, 0, s2>>>(d_cnt, d_cursor, d_bsums, d_dis, n);
    scan2_kernel<<<1, 1024, 0, s2>>>(d_bsums, nb);
    scan3_kernel<<<nb, 256, 0, s2>>>(d_cursor, d_bsums, d_rowptr, d_cursor, n, E);
    fill_kernel<<<(E + 255) / 256, 256, 0, s2>>>(src, dst, d_dis, d_cursor, d_esrc, d_ewt, E);
    cudaEventRecord(evJoin, s2);

    // Branch B (main stream): weight prep + layer-1 GEMM
    prep_w_kernel<<<40, 256>>>(W1, W2, W3, d_w1h, d_w1l, d_w2h, d_w2l, d_w3h, d_w3l);
    gemm_mma_kernel<128, false><<<gemm_blocks, 256, SMEM_A>>>(x, d_w1h, d_w1l, d_h, n);

    // Join: agg1 needs both branches
    cudaStreamWaitEvent(0, evJoin, 0);

    // Layer 1 aggregate
    agg_kernel<128><<<agg128_blocks, 256>>>(d_rowptr, d_esrc, d_ewt, d_h, d_dis, b1, d_bufA, n);

    // Layer 2
    gemm_mma_kernel<128, true><<<gemm_blocks, 256, SMEM_A>>>(d_bufA, d_w2h, d_w2l, d_h, n);
    agg_kernel<128><<<agg128_blocks, 256>>>(d_rowptr, d_esrc, d_ewt, d_h, d_dis, b2, d_bufB, n);

    // Layer 3 (DOUT=64)
    gemm_mma_kernel<64, true><<<gemm_blocks, 256, SMEM_A>>>(d_bufB, d_w3h, d_w3l, d_h, n);
    agg_kernel<64><<<agg64_blocks, 256>>>(d_rowptr, d_esrc, d_ewt, d_h, d_dis, b3, d_bufA, n);

    // Decode
    decode_kernel<<<((EL * 16) + 255) / 256, 256>>>(d_bufA, eli, out_hidden, out_logits, EL);
}

// round 16
// speedup vs baseline: 1.1031x; 1.0665x over previous
#include <cuda_runtime.h>
#include <cuda_fp16.h>
#include <cstdio>
#include <cstdint>

// Problem constants: N=100000, E=1.6M, EL=200000
#define NMAX 100000
#define EMAX 1600000

// Scratch (static __device__ arrays — no allocation allowed)
__device__ float g_dis[NMAX];
__device__ int   g_cnt[NMAX];
__device__ int   g_rowptr[NMAX + 1];
__device__ int   g_cursor[NMAX];
__device__ int   g_bsums[1024];
__device__ int   g_esrc[EMAX];
__device__ float g_ewt[EMAX];
__device__ float g_h[NMAX * 128];
__device__ float g_bufA[NMAX * 128];
__device__ float g_bufB[NMAX * 128];
// Fragment-ordered fp16 weights (mma.sync .col B fragments), hi only:
// A is split hi+lo (22-bit), B is fp16 hi (error 2^-12 ~ 2.4e-4, within budget)
__device__ __half g_w1h[128 * 128];
__device__ __half g_w2h[128 * 128];
__device__ __half g_w3h[64 * 128];

// ---------------------------------------------------------------------------
// PTX helpers (baseline sm_80+ features only — no tcgen05 in this harness)
// ---------------------------------------------------------------------------
__device__ __forceinline__ uint32_t smem_u32(const void* p) {
    uint32_t a;
    asm("{ .reg .u64 t; cvta.to.shared.u64 t, %1; cvt.u32.u64 %0, t; }" : "=r"(a) : "l"(p));
    return a;
}
__device__ __forceinline__ void ldsm_x4(uint32_t* r, uint32_t addr) {
    asm volatile("ldmatrix.sync.aligned.m8n8.x4.shared.b16 {%0,%1,%2,%3}, [%4];"
                 : "=r"(r[0]), "=r"(r[1]), "=r"(r[2]), "=r"(r[3]) : "r"(addr));
}
__device__ __forceinline__ void mma16816h(float* d, const uint32_t* a, uint32_t b0, uint32_t b1) {
    asm volatile("mma.sync.aligned.m16n8k16.row.col.f32.f16.f16.f32 "
                 "{%0,%1,%2,%3}, {%4,%5,%6,%7}, {%8,%9}, {%0,%1,%2,%3};"
                 : "+f"(d[0]), "+f"(d[1]), "+f"(d[2]), "+f"(d[3])
                 : "r"(a[0]), "r"(a[1]), "r"(a[2]), "r"(a[3]), "r"(b0), "r"(b1));
}
__device__ __forceinline__ uint32_t pack_h2(float x, float y) {
    __half2 v = __floats2half2_rn(x, y);
    return *reinterpret_cast<uint32_t*>(&v);
}

// ---------------------------------------------------------------------------
// Weight prep -> fragment-ordered fp16 arrays (hi only).
// Fragment entry j = (ntile*8 + ktile)*32 + lane:
//   n  = ntile*8 + lane/4 ; k0 = ktile*16 + (lane%4)*2
//   b0 = pack(B[k0][n], B[k0+1][n]),  b1 = pack(B[k0+8][n], B[k0+9][n])
// ---------------------------------------------------------------------------
__global__ void prep_w_kernel(const float* __restrict__ W1, const float* __restrict__ W2,
                              const float* __restrict__ W3,
                              __half* __restrict__ w1h, __half* __restrict__ w2h,
                              __half* __restrict__ w3h)
{
    int i = blockIdx.x * blockDim.x + threadIdx.x;
    const float* W; uint2* oh; int dout, j;
    if (i < 4096)       { W = W1; oh = (uint2*)w1h; dout = 128; j = i; }
    else if (i < 8192)  { W = W2; oh = (uint2*)w2h; dout = 128; j = i - 4096; }
    else if (i < 10240) { W = W3; oh = (uint2*)w3h; dout = 64;  j = i - 8192; }
    else return;

    int lane  = j & 31;
    int ktile = (j >> 5) & 7;
    int ntile = j >> 8;
    int n  = ntile * 8 + (lane >> 2);
    int k0 = ktile * 16 + (lane & 3) * 2;

    uint2 hv;
    hv.x = pack_h2(W[(k0 + 0) * dout + n], W[(k0 + 1) * dout + n]);
    hv.y = pack_h2(W[(k0 + 8) * dout + n], W[(k0 + 9) * dout + n]);
    oh[j] = hv;
}

// ---------------------------------------------------------------------------
// mma.sync fp16-split GEMM: h = relu?(in) @ W   (64 regs, occ 4 — proven)
// Block: 256 thr, 64 rows x DOUT cols, K=128. Warp grid 2x4.
// A staged in smem as fp16 hi/lo (22-bit total) + ldmatrix; B fp16 hi
// fragments LDG'd from fragment-ordered global arrays.
// 2 products: Ah*Bh + Al*Bh (fp32 accum). B rounding (2^-12) dominates
// error: ~2e-4 final, 5x under the 1e-3 threshold.
// ---------------------------------------------------------------------------
template <int DOUT, bool RELU_IN>
__global__ void __launch_bounds__(256, 4)
gemm_mma_kernel(const float* __restrict__ in, const __half* __restrict__ wtHi,
                float* __restrict__ h, int n)
{
    constexpr int THREADS = 256;
    constexpr int ROWS = 64;
    constexpr int K = 128;
    constexpr int PITCH = 136;                   // halfwords per smem row
    constexpr int TN = DOUT / 4;                 // warp tile cols (32 or 16)
    constexpr int NT = TN / 8;                   // n-tiles per warp (4 or 2)
    constexpr int A_HI = 0;
    constexpr int A_LO = ROWS * PITCH;           // 8704

    extern __shared__ __half smem[];
    const int t = threadIdx.x;
    const int row0 = blockIdx.x * ROWS;

    // ---- Stage A (fp32 -> hi/lo fp16, ReLU folded) ----
    const float4* in4 = reinterpret_cast<const float4*>(in);
    #pragma unroll
    for (int i = t; i < ROWS * (K / 4); i += THREADS) {
        int r = i >> 5, c4 = i & 31;
        int gr = row0 + r;
        float4 v = make_float4(0.f, 0.f, 0.f, 0.f);
        if (gr < n) v = in4[(size_t)gr * (K / 4) + c4];
        if (RELU_IN) {
            v.x = fmaxf(v.x, 0.f); v.y = fmaxf(v.y, 0.f);
            v.z = fmaxf(v.z, 0.f); v.w = fmaxf(v.w, 0.f);
        }
        __half hx = __float2half_rn(v.x), hy = __float2half_rn(v.y);
        __half hz = __float2half_rn(v.z), hw = __float2half_rn(v.w);
        uint32_t h0 = pack_h2(v.x, v.y);           // same rounding as hx,hy
        uint32_t h1 = pack_h2(v.z, v.w);
        uint32_t l0 = pack_h2(v.x - __half2float(hx), v.y - __half2float(hy));
        uint32_t l1 = pack_h2(v.z - __half2float(hz), v.w - __half2float(hw));
        int off = r * PITCH + c4 * 4;
        *reinterpret_cast<uint2*>(smem + A_HI + off) = make_uint2(h0, h1);
        *reinterpret_cast<uint2*>(smem + A_LO + off) = make_uint2(l0, l1);
    }
    __syncthreads();

    // ---- Fragment addresses ----
    const int wid  = t >> 5;
    const int lane = t & 31;
    const int warpM = wid >> 2;   // 0..1
    const int warpN = wid & 3;    // 0..3

    const int aRow = warpM * 32 + (lane & 15);
    const int aCol = (lane >> 4) * 8;
    const uint32_t sb = smem_u32(smem);
    const uint32_t aHiAddr = sb + (uint32_t)(A_HI + aRow * PITCH + aCol) * 2;
    const uint32_t aLoAddr = aHiAddr + (uint32_t)(A_LO - A_HI) * 2;

    const uint2* fH = reinterpret_cast<const uint2*>(wtHi);
    const int fbase = (warpN * NT) * 256 + lane;   // ntile stride = 8*32 = 256

    float acc[2][NT][4];
    #pragma unroll
    for (int mt = 0; mt < 2; ++mt)
        #pragma unroll
        for (int nt = 0; nt < NT; ++nt)
            #pragma unroll
            for (int r = 0; r < 4; ++r) acc[mt][nt][r] = 0.f;

    #pragma unroll
    for (int kt = 0; kt < 8; ++kt) {
        const uint32_t ka = kt * 32;          // 16 halfwords = 32 bytes per k-tile
        uint32_t ah[2][4], al[2][4];
        uint2 bh[NT];
        // Issue all loads up front
        ldsm_x4(ah[0], aHiAddr + ka);
        ldsm_x4(ah[1], aHiAddr + ka + 16 * PITCH * 2);
        #pragma unroll
        for (int nt = 0; nt < NT; ++nt) bh[nt] = __ldg(&fH[fbase + nt * 256 + kt * 32]);
        ldsm_x4(al[0], aLoAddr + ka);
        ldsm_x4(al[1], aLoAddr + ka + 16 * PITCH * 2);

        // hi * hi
        #pragma unroll
        for (int mt = 0; mt < 2; ++mt)
            #pragma unroll
            for (int nt = 0; nt < NT; ++nt)
                mma16816h(acc[mt][nt], ah[mt], bh[nt].x, bh[nt].y);
        // lo * hi (A correction)
        #pragma unroll
        for (int mt = 0; mt < 2; ++mt)
            #pragma unroll
            for (int nt = 0; nt < NT; ++nt)
                mma16816h(acc[mt][nt], al[mt], bh[nt].x, bh[nt].y);
    }

    // ---- Epilogue: direct float2 stores from fragments ----
    float2* h2 = reinterpret_cast<float2*>(h);
    #pragma unroll
    for (int mt = 0; mt < 2; ++mt) {
        #pragma unroll
        for (int nt = 0; nt < NT; ++nt) {
            int r = row0 + warpM * 32 + mt * 16 + (lane >> 2);
            int c = warpN * TN + nt * 8 + 2 * (lane & 3);
            if (r < n)
                h2[(size_t)r * (DOUT / 2) + c / 2] = make_float2(acc[mt][nt][0], acc[mt][nt][1]);
            if (r + 8 < n)
                h2[(size_t)(r + 8) * (DOUT / 2) + c / 2] = make_float2(acc[mt][nt][2], acc[mt][nt][3]);
        }
    }
}

// ---------------------------------------------------------------------------
// CSR build kernels
// ---------------------------------------------------------------------------
__global__ void zero_cnt_kernel(int* __restrict__ cnt, int n) {
    int i = blockIdx.x * blockDim.x + threadIdx.x;
    if (i < n) cnt[i] = 0;
}

__global__ void count_kernel(int* __restrict__ cnt, const int* __restrict__ dst, int E) {
    int e = blockIdx.x * blockDim.x + threadIdx.x;
    if (e < E) atomicAdd(&cnt[dst[e]], 1);
}

__global__ void scan1_kernel(const int* __restrict__ cnt, int* __restrict__ part,
                             int* __restrict__ sums, float* __restrict__ dis, int n) {
    __shared__ int sm[256];
    int t = threadIdx.x;
    int i = blockIdx.x * 256 + t;
    int v = (i < n) ? cnt[i] : 0;
    if (i < n) dis[i] = rsqrtf((float)(v + 1));
    sm[t] = v;
    __syncthreads();
    #pragma unroll
    for (int off = 1; off < 256; off <<= 1) {
        int a = (t >= off) ? sm[t - off] : 0;
        __syncthreads();
        sm[t] += a;
        __syncthreads();
    }
    if (i < n) part[i] = sm[t] - v;
    if (t == 255) sums[blockIdx.x] = sm[255];
}

__global__ void scan2_kernel(int* __restrict__ sums, int nb) {
    __shared__ int sm[1024];
    int t = threadIdx.x;
    int v = (t < nb) ? sums[t] : 0;
    sm[t] = v;
    __syncthreads();
    #pragma unroll
    for (int off = 1; off < 1024; off <<= 1) {
        int a = (t >= off) ? sm[t - off] : 0;
        __syncthreads();
        sm[t] += a;
        __syncthreads();
    }
    if (t < nb) sums[t] = sm[t] - v;
}

__global__ void scan3_kernel(const int* __restrict__ part, const int* __restrict__ sums,
                             int* __restrict__ row_ptr, int* __restrict__ cursor,
                             int n, int E) {
    int i = blockIdx.x * blockDim.x + threadIdx.x;
    if (i < n) {
        int v = part[i] + sums[i >> 8];
        row_ptr[i] = v;
        cursor[i] = v;
    }
    if (i == 0) row_ptr[n] = E;
}

__global__ void fill_kernel(const int* __restrict__ src, const int* __restrict__ dst,
                            const float* __restrict__ dis,
                            int* __restrict__ cursor, int* __restrict__ esrc,
                            float* __restrict__ ewt, int E) {
    int e = blockIdx.x * blockDim.x + threadIdx.x;
    if (e >= E) return;
    int s = src[e];
    int d = dst[e];
    int pos = atomicAdd(&cursor[d], 1);
    esrc[pos] = s;
    ewt[pos] = dis[s] * dis[d];
}

// ---------------------------------------------------------------------------
// CSR gather-aggregate with fused self-loop + bias (unroll-4: proven optimal)
// ---------------------------------------------------------------------------
template <int D>
__global__ void __launch_bounds__(256)
agg_kernel(const int* __restrict__ rp, const int* __restrict__ esrc,
           const float* __restrict__ ewt, const float* __restrict__ h,
           const float* __restrict__ dis, const float* __restrict__ bias,
           float* __restrict__ out, int n)
{
    constexpr int G = D / 4;
    int tid = blockIdx.x * blockDim.x + threadIdx.x;
    int node = tid / G;
    int li   = tid % G;
    if (node >= n) return;

    int beg = rp[node];
    int end = rp[node + 1];

    const float4* h4 = reinterpret_cast<const float4*>(h);

    float d = dis[node];
    float dd = d * d;
    float4 hv = h4[(size_t)node * G + li];
    float4 b4 = reinterpret_cast<const float4*>(bias)[li];
    float4 acc;
    acc.x = fmaf(dd, hv.x, b4.x);
    acc.y = fmaf(dd, hv.y, b4.y);
    acc.z = fmaf(dd, hv.z, b4.z);
    acc.w = fmaf(dd, hv.w, b4.w);

    int j = beg;
    for (; j + 4 <= end; j += 4) {
        int s0 = esrc[j], s1 = esrc[j + 1], s2 = esrc[j + 2], s3 = esrc[j + 3];
        float w0 = ewt[j], w1 = ewt[j + 1], w2 = ewt[j + 2], w3 = ewt[j + 3];
        float4 v0 = h4[(size_t)s0 * G + li];
        float4 v1 = h4[(size_t)s1 * G + li];
        float4 v2 = h4[(size_t)s2 * G + li];
        float4 v3 = h4[(size_t)s3 * G + li];
        acc.x = fmaf(w0, v0.x, fmaf(w1, v1.x, fmaf(w2, v2.x, fmaf(w3, v3.x, acc.x))));
        acc.y = fmaf(w0, v0.y, fmaf(w1, v1.y, fmaf(w2, v2.y, fmaf(w3, v3.y, acc.y))));
        acc.z = fmaf(w0, v0.z, fmaf(w1, v1.z, fmaf(w2, v2.z, fmaf(w3, v3.z, acc.z))));
        acc.w = fmaf(w0, v0.w, fmaf(w1, v1.w, fmaf(w2, v2.w, fmaf(w3, v3.w, acc.w))));
    }
    for (; j < end; ++j) {
        int s = esrc[j];
        float w = ewt[j];
        float4 v = h4[(size_t)s * G + li];
        acc.x = fmaf(w, v.x, acc.x);
        acc.y = fmaf(w, v.y, acc.y);
        acc.z = fmaf(w, v.z, acc.z);
        acc.w = fmaf(w, v.w, acc.w);
    }

    reinterpret_cast<float4*>(out)[(size_t)node * G + li] = acc;
}

// ---------------------------------------------------------------------------
// Decode
// ---------------------------------------------------------------------------
__global__ void __launch_bounds__(256)
decode_kernel(const float* __restrict__ z, const int* __restrict__ eli,
              float* __restrict__ outh, float* __restrict__ outl, int EL)
{
    int tid = blockIdx.x * blockDim.x + threadIdx.x;
    int eid = tid >> 4;
    int li  = tid & 15;
    int lane = threadIdx.x & 31;
    unsigned mask = 0xFFFFu << (lane & 16);

    if (eid >= EL) return;

    int s = eli[eid];
    int t = eli[EL + eid];
    const float4* z4 = reinterpret_cast<const float4*>(z);
    float4 a = z4[(size_t)s * 16 + li];
    float4 b = z4[(size_t)t * 16 + li];

    float4 hh;
    hh.x = a.x * b.x; hh.y = a.y * b.y; hh.z = a.z * b.z; hh.w = a.w * b.w;

    float sum = hh.x + hh.y + hh.z + hh.w;
    float sq  = hh.x * hh.x + hh.y * hh.y + hh.z * hh.z + hh.w * hh.w;

    #pragma unroll
    for (int off = 8; off > 0; off >>= 1) {
        sum += __shfl_xor_sync(mask, sum, off);
        sq  += __shfl_xor_sync(mask, sq,  off);
    }

    float nrm = sqrtf(sq);
    float inv = 1.0f / fmaxf(nrm, 1e-12f);
    float4 o;
    o.x = hh.x * inv; o.y = hh.y * inv; o.z = hh.z * inv; o.w = hh.w * inv;
    reinterpret_cast<float4*>(outh)[(size_t)eid * 16 + li] = o;
    if (li == 0) outl[eid] = sum;
}

// ---------------------------------------------------------------------------
// Launch — R13 structure: CSR build forked onto a second stream, concurrent
// with prep_w + gemm1 in the captured graph. Streams/events created per call
// and not destroyed (capture-safe; no device-memory allocation APIs).
// ---------------------------------------------------------------------------
extern "C" void kernel_launch(void* const* d_in, const int* in_sizes, int n_in,
                              void* d_out, int out_size)
{
    const float* x   = (const float*)d_in[0];
    const float* W1  = (const float*)d_in[1];
    const float* b1  = (const float*)d_in[2];
    const float* W2  = (const float*)d_in[3];
    const float* b2  = (const float*)d_in[4];
    const float* W3  = (const float*)d_in[5];
    const float* b3  = (const float*)d_in[6];
    const int*   ei  = (const int*)d_in[7];
    const int*   eli = (const int*)d_in[8];

    const int n  = in_sizes[0] / 128;
    const int E  = in_sizes[7] / 2;
    const int EL = in_sizes[8] / 2;

    float* out = (float*)d_out;
    float* out_hidden = out;
    float* out_logits = out + (size_t)EL * 64;

    float *d_dis, *d_h, *d_bufA, *d_bufB, *d_ewt;
    int *d_cnt, *d_rowptr, *d_cursor, *d_bsums, *d_esrc;
    __half *d_w1h, *d_w2h, *d_w3h;
    cudaGetSymbolAddress((void**)&d_dis,    g_dis);
    cudaGetSymbolAddress((void**)&d_cnt,    g_cnt);
    cudaGetSymbolAddress((void**)&d_rowptr, g_rowptr);
    cudaGetSymbolAddress((void**)&d_cursor, g_cursor);
    cudaGetSymbolAddress((void**)&d_bsums,  g_bsums);
    cudaGetSymbolAddress((void**)&d_esrc,   g_esrc);
    cudaGetSymbolAddress((void**)&d_ewt,    g_ewt);
    cudaGetSymbolAddress((void**)&d_h,      g_h);
    cudaGetSymbolAddress((void**)&d_bufA,   g_bufA);
    cudaGetSymbolAddress((void**)&d_bufB,   g_bufB);
    cudaGetSymbolAddress((void**)&d_w1h,    g_w1h);
    cudaGetSymbolAddress((void**)&d_w2h,    g_w2h);
    cudaGetSymbolAddress((void**)&d_w3h,    g_w3h);

    // smem: A hi/lo only (2*64*136*2 B)
    constexpr int SMEM_A = 2 * 64 * 136 * 2;   // 34816
    cudaFuncSetAttribute(gemm_mma_kernel<128, false>, cudaFuncAttributeMaxDynamicSharedMemorySize, SMEM_A);
    cudaFuncSetAttribute(gemm_mma_kernel<128, true>,  cudaFuncAttributeMaxDynamicSharedMemorySize, SMEM_A);
    cudaFuncSetAttribute(gemm_mma_kernel<64,  true>,  cudaFuncAttributeMaxDynamicSharedMemorySize, SMEM_A);

    const int* src = ei;
    const int* dst = ei + E;

    const int nb = (n + 255) / 256;
    const int gemm_blocks = (n + 63) / 64;
    const int agg128_blocks = ((n * 32) + 255) / 256;
    const int agg64_blocks  = ((n * 16) + 255) / 256;

    // ---- Fork a side stream for the CSR build ----
    cudaStream_t s2;
    cudaStreamCreateWithFlags(&s2, cudaStreamNonBlocking);
    cudaEvent_t evFork, evJoin;
    cudaEventCreateWithFlags(&evFork, cudaEventDisableTiming);
    cudaEventCreateWithFlags(&evJoin, cudaEventDisableTiming);

    cudaEventRecord(evFork, 0);
    cudaStreamWaitEvent(s2, evFork, 0);

    // Branch A (s2): CSR build — independent of weights/gemm1
    zero_cnt_kernel<<<nb, 256, 0, s2>>>(d_cnt, n);
    count_kernel<<<(E + 255) / 256, 256, 0, s2>>>(d_cnt, dst, E);
    scan1_kernel<<<nb, 256, 0, s2>>>(d_cnt, d_cursor, d_bsums, d_dis, n);
    scan2_kernel<<<1, 1024, 0, s2>>>(d_bsums, nb);
    scan3_kernel<<<nb, 256, 0, s2>>>(d_cursor, d_bsums, d_rowptr, d_cursor, n, E);
    fill_kernel<<<(E + 255) / 256, 256, 0, s2>>>(src, dst, d_dis, d_cursor, d_esrc, d_ewt, E);
    cudaEventRecord(evJoin, s2);

    // Branch B (main stream): weight prep + layer-1 GEMM
    prep_w_kernel<<<40, 256>>>(W1, W2, W3, d_w1h, d_w2h, d_w3h);
    gemm_mma_kernel<128, false><<<gemm_blocks, 256, SMEM_A>>>(x, d_w1h, d_h, n);

    // Join: agg1 needs both branches
    cudaStreamWaitEvent(0, evJoin, 0);

    // Layer 1 aggregate
    agg_kernel<128><<<agg128_blocks, 256>>>(d_rowptr, d_esrc, d_ewt, d_h, d_dis, b1, d_bufA, n);

    // Layer 2
    gemm_mma_kernel<128, true><<<gemm_blocks, 256, SMEM_A>>>(d_bufA, d_w2h, d_h, n);
    agg_kernel<128><<<agg128_blocks, 256>>>(d_rowptr, d_esrc, d_ewt, d_h, d_dis, b2, d_bufB, n);

    // Layer 3 (DOUT=64)
    gemm_mma_kernel<64, true><<<gemm_blocks, 256, SMEM_A>>>(d_bufB, d_w3h, d_h, n);
    agg_kernel<64><<<agg64_blocks, 256>>>(d_rowptr, d_esrc, d_ewt, d_h, d_dis, b3, d_bufA, n);

    // Decode
    decode_kernel<<<((EL * 16) + 255) / 256, 256>>>(d_bufA, eli, out_hidden, out_logits, EL);
}